// round 15
// baseline (speedup 1.0000x reference)
#include <cuda_runtime.h>
#include <cuda_fp16.h>
#include <math.h>
#include <cstdint>

#define S_LEN  2048
#define HID    2048
#define NH     16
#define QLORA  1536
#define KVLORA 512
#define NOPE   128
#define ROPED  64
#define VD     128
#define QHD    192
#define KVD    256
#define NC     2112                  // QLORA + KVLORA + ROPED

// ---------------- scratch ----------------
__device__ float  g_qc   [S_LEN * NC];
__device__ float  g_qbuf [S_LEN * NH * QHD];
__device__ __half g_kv16 [S_LEN * NH * KVD];
__device__ __half g_kpe16[S_LEN * ROPED];
__device__ __half g_h16     [S_LEN * HID];
__device__ __half g_wqakva16[NC * HID];
__device__ __half g_wqb16   [NH * QHD * QLORA];
__device__ __half g_wkvb16  [NH * KVD * KVLORA];
__device__ __half g_wo16    [HID * NH * VD];
__device__ __half g_qlat16  [S_LEN * QLORA];
__device__ __half g_ckvn16  [S_LEN * KVLORA];
__device__ __half g_attn16  [S_LEN * NH * VD];

// ======================= helpers =======================
__device__ __forceinline__ uint32_t smem_u32(const void* p) {
    uint32_t a;
    asm("{ .reg .u64 t; cvta.to.shared.u64 t, %1; cvt.u32.u64 %0, t; }"
        : "=r"(a) : "l"(p));
    return a;
}
__device__ __forceinline__ uint32_t packh2(float a, float b) {
    __half2 h = __floats2half2_rn(a, b);
    return *(uint32_t*)&h;
}
__device__ __forceinline__ void mma_f16(float* d, uint32_t a0, uint32_t a1,
                                        uint32_t a2, uint32_t a3,
                                        uint32_t b0, uint32_t b1) {
    asm volatile(
        "mma.sync.aligned.m16n8k16.row.col.f32.f16.f16.f32 "
        "{%0,%1,%2,%3}, {%4,%5,%6,%7}, {%8,%9}, {%0,%1,%2,%3};"
        : "+f"(d[0]), "+f"(d[1]), "+f"(d[2]), "+f"(d[3])
        : "r"(a0), "r"(a1), "r"(a2), "r"(a3), "r"(b0), "r"(b1));
}
__device__ __forceinline__ void ldsm_x4_t(uint32_t& r0, uint32_t& r1,
                                          uint32_t& r2, uint32_t& r3,
                                          uint32_t addr) {
    asm volatile(
        "ldmatrix.sync.aligned.m8n8.x4.trans.shared.b16 {%0,%1,%2,%3}, [%4];"
        : "=r"(r0), "=r"(r1), "=r"(r2), "=r"(r3) : "r"(addr));
}

// -------- fused float -> half convert: block-uniform, 4x float4/thread ------
#define G0 1024
#define G1 (G0 + 768)
#define G2 (G1 + 288)
#define G3 (G2 + 1152)
#define G4 (G3 + 512)
#define G5 (G4 + 1024)

__global__ __launch_bounds__(256) void f2h_all_kernel(
    const float* __restrict__ s0, __half* __restrict__ d0,
    const float* __restrict__ s1, __half* __restrict__ d1,
    const float* __restrict__ s2, __half* __restrict__ d2,
    const float* __restrict__ s3, __half* __restrict__ d3,
    const float* __restrict__ s4, __half* __restrict__ d4,
    const float* __restrict__ s5, __half* __restrict__ d5)
{
    const int b = blockIdx.x;
    const float* s; __half* d; int lb;
    if      (b < G0) { s = s0; d = d0; lb = b; }
    else if (b < G1) { s = s1; d = d1; lb = b - G0; }
    else if (b < G2) { s = s2; d = d2; lb = b - G1; }
    else if (b < G3) { s = s3; d = d3; lb = b - G2; }
    else if (b < G4) { s = s4; d = d4; lb = b - G3; }
    else             { s = s5; d = d5; lb = b - G4; }
    const int base = lb * 1024 + threadIdx.x;
#pragma unroll
    for (int k = 0; k < 4; k++) {
        const int j = base + k * 256;
        float4 v = ((const float4*)s)[j];
        uint2 o;
        o.x = packh2(v.x, v.y);
        o.y = packh2(v.z, v.w);
        *(uint2*)(d + 4 * j) = o;
    }
}

// ============ fp16 mma.sync GEMM: C[M,N] = A[M,K] @ B[N,K]^T ============
// CTA 128x128, warp 32x64. K-tile 64 stored as two K-32 sub-tiles
// (conflict-free stride-32 layout preserved). 2 stages x 32KB, 2 CTAs/SM,
// unroll-2 (NT = K/64 even for K = 2048/1536/512). One sync per 64-K.
#define SUBT   4096                    // halves per sub-tile (128x32)
#define STGH   16384                   // halves per stage (A0 A1 B0 B1)
#define STGB   32768                   // bytes per stage
#define GEMM_SMEM (2 * STGB)           // 65536 bytes

template <int HALF_OUT>
__global__ __launch_bounds__(256, 2) void gemm_h(
    const __half* __restrict__ A, const __half* __restrict__ B,
    void* __restrict__ Cv, int M, int N, int K)
{
    extern __shared__ __half smh[];
    const int tid  = threadIdx.x;
    const int lane = tid & 31;
    const int w    = tid >> 5;
    const int g    = lane >> 2;
    const int t    = lane & 3;
    const int wm   = w & 3;
    const int wn   = w >> 2;
    const int bm   = blockIdx.y * 128;
    const int bn   = blockIdx.x * 128;

    const uint32_t sbase = smem_u32(smh);
    float acc[2][8][4] = {};
    const int NT = K >> 6;             // K-64 tiles

    // load geometry: thread covers rows row0 + i*32 (i=0..3), cols c8..c8+7
    const int row0 = tid >> 3;         // 0..31
    const int c8   = (tid & 7) * 8;    // 0..56
    const int sub  = (tid & 7) >> 2;   // 0 or 1 (k-32 sub-tile)
    const int off  = c8 & 31;          // 0,8,16,24
    const __half* aS = A + (size_t)(bm + row0) * K + c8;
    const __half* bS = B + (size_t)(bn + row0) * K + c8;
    const size_t rS = (size_t)32 * K;  // row-block stride (halves)
    int szb[4];
#pragma unroll
    for (int i = 0; i < 4; i++) szb[i] = (bn + row0 + i * 32 < N) ? 16 : 0;
    const uint32_t aD = sbase + (sub * SUBT + row0 * 32 + off) * 2;
    const uint32_t bD = aD + 2 * SUBT * 2;   // B region after A0|A1

    auto issue = [&](int kt, uint32_t so) {
        if (kt < NT) {
            const size_t o = (size_t)kt * 64;
#pragma unroll
            for (int i = 0; i < 4; i++) {
                asm volatile("cp.async.ca.shared.global [%0], [%1], 16;"
                             :: "r"(aD + so + i * 2048), "l"(aS + i * rS + o)
                             : "memory");
                asm volatile("cp.async.ca.shared.global [%0], [%1], 16, %2;"
                             :: "r"(bD + so + i * 2048), "l"(bS + i * rS + o),
                                "r"(szb[i]) : "memory");
            }
        }
        asm volatile("cp.async.commit_group;" ::: "memory");
    };

    issue(0, 0);

    const int aOff = wm * 32 * 32 + g * 32 + 8 * t;          // within sub-tile
    const int bOff = 2 * SUBT + wn * 64 * 32 + g * 32 + 8 * t;

    for (int kt = 0; kt < NT; kt += 2) {
#pragma unroll
        for (int j = 0; j < 2; j++) {
            asm volatile("cp.async.wait_group 0;" ::: "memory");
            __syncthreads();
            issue(kt + j + 1, (uint32_t)(((j + 1) & 1) * STGB));

            const __half* stg = smh + (j & 1) * STGH;
#pragma unroll
            for (int kk = 0; kk < 2; kk++) {
                const __half* Asp = stg + kk * SUBT + aOff;
                const __half* Bsp = stg + kk * SUBT + bOff;

                uint4 a4[4], b4[8];
#pragma unroll
                for (int rr = 0; rr < 4; rr++)
                    a4[rr] = *(const uint4*)(Asp + rr * 8 * 32);
#pragma unroll
                for (int nt = 0; nt < 8; nt++)
                    b4[nt] = *(const uint4*)(Bsp + nt * 8 * 32);

#pragma unroll
                for (int s = 0; s < 2; s++) {
#pragma unroll
                    for (int mt = 0; mt < 2; mt++) {
                        const uint32_t A0 = s ? a4[2 * mt].z     : a4[2 * mt].x;
                        const uint32_t A1 = s ? a4[2 * mt + 1].z : a4[2 * mt + 1].x;
                        const uint32_t A2 = s ? a4[2 * mt].w     : a4[2 * mt].y;
                        const uint32_t A3 = s ? a4[2 * mt + 1].w : a4[2 * mt + 1].y;
#pragma unroll
                        for (int nt = 0; nt < 8; nt++) {
                            const uint32_t B0 = s ? b4[nt].z : b4[nt].x;
                            const uint32_t B1 = s ? b4[nt].w : b4[nt].y;
                            mma_f16(acc[mt][nt], A0, A1, A2, A3, B0, B1);
                        }
                    }
                }
            }
        }
    }

#pragma unroll
    for (int mt = 0; mt < 2; mt++) {
        const int row = bm + wm * 32 + mt * 16 + g;
#pragma unroll
        for (int nt = 0; nt < 8; nt++) {
            const int col = bn + wn * 64 + nt * 8 + 2 * t;
            if (col < N) {
                if (HALF_OUT) {
                    __half* C = (__half*)Cv;
                    *(__half2*)&C[(size_t)row * N + col] =
                        __floats2half2_rn(acc[mt][nt][0], acc[mt][nt][1]);
                    *(__half2*)&C[(size_t)(row + 8) * N + col] =
                        __floats2half2_rn(acc[mt][nt][2], acc[mt][nt][3]);
                } else {
                    float* C = (float*)Cv;
                    *(float2*)&C[(size_t)row * N + col] =
                        make_float2(acc[mt][nt][0], acc[mt][nt][1]);
                    *(float2*)&C[(size_t)(row + 8) * N + col] =
                        make_float2(acc[mt][nt][2], acc[mt][nt][3]);
                }
            }
        }
    }
}

// ---------------- fused RMSNorm: y==0 -> qlat, y==1 -> ckv ----------------
__global__ __launch_bounds__(256) void rmsnorm2_kernel(
    const float* __restrict__ qc, const float* __restrict__ wq,
    const float* __restrict__ wkv, __half* __restrict__ yq,
    __half* __restrict__ ykv)
{
    const int row = blockIdx.x;
    const float* xr;
    const float* w;
    __half* yr;
    int ncols;
    if (blockIdx.y == 0) {
        xr = qc + (size_t)row * NC;          w = wq;  yr = yq + (size_t)row * QLORA;
        ncols = QLORA;
    } else {
        xr = qc + (size_t)row * NC + QLORA;  w = wkv; yr = ykv + (size_t)row * KVLORA;
        ncols = KVLORA;
    }
    const int n4 = ncols >> 2;

    float ss = 0.f;
    for (int c = threadIdx.x; c < n4; c += 256) {
        float4 v = ((const float4*)xr)[c];
        ss += v.x * v.x + v.y * v.y + v.z * v.z + v.w * v.w;
    }
    __shared__ float red[8];
#pragma unroll
    for (int o = 16; o; o >>= 1) ss += __shfl_xor_sync(~0u, ss, o);
    if ((threadIdx.x & 31) == 0) red[threadIdx.x >> 5] = ss;
    __syncthreads();
    if (threadIdx.x < 32) {
        float v = (threadIdx.x < 8) ? red[threadIdx.x] : 0.f;
#pragma unroll
        for (int o = 4; o; o >>= 1) v += __shfl_xor_sync(~0u, v, o);
        if (threadIdx.x == 0) red[0] = v;
    }
    __syncthreads();
    const float inv = rsqrtf(red[0] / (float)ncols + 1e-6f);
    for (int c = threadIdx.x; c < n4; c += 256) {
        float4 v = ((const float4*)xr)[c];
        float4 wv = ((const float4*)w)[c];
        uint2 o;
        o.x = packh2(v.x * inv * wv.x, v.y * inv * wv.y);
        o.y = packh2(v.z * inv * wv.z, v.w * inv * wv.w);
        *(uint2*)(yr + 4 * c) = o;
    }
}

// ---------------- RoPE (q fp32 in-place; kpe -> fp16) ----------------
__global__ __launch_bounds__(544) void rope_kernel(
    float* __restrict__ q, const float* __restrict__ qc, __half* __restrict__ kpe)
{
    const int s = blockIdx.x;
    const int t = threadIdx.x;
    const int h = t >> 5;
    const int d = t & 31;

    const float f = powf(10000.0f, -(float)d / 32.0f);
    float sn, cs;
    sincosf((float)s * f, &sn, &cs);

    if (h < NH) {
        float* p = q + (size_t)s * (NH * QHD) + h * QHD + NOPE;
        float x1 = p[d], x2 = p[d + 32];
        p[d]      = x1 * cs - x2 * sn;
        p[d + 32] = x2 * cs + x1 * sn;
    } else {
        const float* p = qc + (size_t)s * NC + QLORA + KVLORA;
        float x1 = p[d], x2 = p[d + 32];
        kpe[s * ROPED + d]      = __float2half_rn(x1 * cs - x2 * sn);
        kpe[s * ROPED + d + 32] = __float2half_rn(x2 * cs + x1 * sn);
    }
}

// ======== Flash attention FA2-style: BQ=128, 3-stage KV, 1 sync/iter ========
#define SKH 224
#define VPH 136
#define STG_B 46080
#define ATTN_SMEM (3 * STG_B)

__global__ __launch_bounds__(256) void attn_mma(
    const float* __restrict__ q, const __half* __restrict__ kv16,
    const __half* __restrict__ kpe16, __half* __restrict__ out)
{
    extern __shared__ char smc[];
    const int tid = threadIdx.x, lane = tid & 31, wid = tid >> 5;
    const int g = lane >> 2, t = lane & 3;
    const int qb = (int)gridDim.x - 1 - (int)blockIdx.x;
    const int h  = blockIdx.y;
    const uint32_t sbase = smem_u32(smc);

    uint32_t qf[12][4];
    {
        const float sc = 0.07216878364870323f;
        const float* Qg0 =
            q + (size_t)(qb * 128 + wid * 16 + g) * (NH * QHD) + h * QHD;
        const float* Qg1 = Qg0 + (size_t)8 * (NH * QHD);
#pragma unroll
        for (int m = 0; m < 12; m++) {
            const int kk = 32 * (m >> 1) + 8 * t + 4 * (m & 1);
            qf[m][0] = packh2(sc * Qg0[kk],     sc * Qg0[kk + 1]);
            qf[m][1] = packh2(sc * Qg1[kk],     sc * Qg1[kk + 1]);
            qf[m][2] = packh2(sc * Qg0[kk + 2], sc * Qg0[kk + 3]);
            qf[m][3] = packh2(sc * Qg1[kk + 2], sc * Qg1[kk + 3]);
        }
    }

    float oa[16][4] = {};
    float m0 = -1e30f, m1 = -1e30f, l0 = 0.f, l1 = 0.f;
    const int nkb = 2 * qb + 2;

    auto fill = [&](int kb) {
        if (kb < nkb) {
            const uint32_t kd = sbase + (kb % 3) * STG_B;
            const uint32_t vd = kd + 28672;
#pragma unroll
            for (int i = 0; i < 6; i++) {
                int idx = tid + i * 256;
                int r = idx / 24, c8 = (idx % 24) * 8;
                const __half* src = (c8 < 128)
                    ? (kv16 + (size_t)(kb * 64 + r) * (NH * KVD) + h * KVD + c8)
                    : (kpe16 + (size_t)(kb * 64 + r) * ROPED + (c8 - 128));
                uint32_t d = kd + (r * SKH + c8) * 2;
                asm volatile("cp.async.ca.shared.global [%0], [%1], 16;"
                             :: "r"(d), "l"(src) : "memory");
            }
            const __half* vsrc =
                kv16 + (size_t)(kb * 64) * (NH * KVD) + h * KVD + NOPE;
#pragma unroll
            for (int i = 0; i < 4; i++) {
                int idx = tid + i * 256;
                int r = idx >> 4, c8 = (idx & 15) * 8;
                uint32_t d = vd + (r * VPH + c8) * 2;
                asm volatile("cp.async.ca.shared.global [%0], [%1], 16;"
                             :: "r"(d), "l"(vsrc + (size_t)r * (NH * KVD) + c8)
                             : "memory");
            }
        }
        asm volatile("cp.async.commit_group;" ::: "memory");
    };

    fill(0); fill(1);

    const int r0g = qb * 128 + wid * 16 + g;
    const int r1g = r0g + 8;

    for (int kb = 0; kb < nkb; kb++) {
        asm volatile("cp.async.wait_group 1;" ::: "memory");
        __syncthreads();
        fill(kb + 2);

        const __half* Ks = (const __half*)(smc + (kb % 3) * STG_B);
        const uint32_t vbase = sbase + (kb % 3) * STG_B + 28672;

        float sf[8][4] = {};
#pragma unroll
        for (int s2 = 0; s2 < 6; s2++) {
            const int co = s2 * 32 + 8 * t;
            uint4 k4[8];
#pragma unroll
            for (int nt = 0; nt < 8; nt++)
                k4[nt] = *(const uint4*)(Ks + (nt * 8 + g) * SKH + co);
#pragma unroll
            for (int nt = 0; nt < 8; nt++) {
                mma_f16(sf[nt], qf[2 * s2][0], qf[2 * s2][1],
                        qf[2 * s2][2], qf[2 * s2][3], k4[nt].x, k4[nt].y);
                mma_f16(sf[nt], qf[2 * s2 + 1][0], qf[2 * s2 + 1][1],
                        qf[2 * s2 + 1][2], qf[2 * s2 + 1][3], k4[nt].z, k4[nt].w);
            }
        }

        float pm0 = -1e30f, pm1 = -1e30f;
        const bool diag = (kb >= 2 * qb);
#pragma unroll
        for (int nt = 0; nt < 8; nt++) {
            const int c = kb * 64 + nt * 8 + 2 * t;
            if (diag) {
                if (c     > r0g) sf[nt][0] = -1e30f;
                if (c + 1 > r0g) sf[nt][1] = -1e30f;
                if (c     > r1g) sf[nt][2] = -1e30f;
                if (c + 1 > r1g) sf[nt][3] = -1e30f;
            }
            pm0 = fmaxf(pm0, fmaxf(sf[nt][0], sf[nt][1]));
            pm1 = fmaxf(pm1, fmaxf(sf[nt][2], sf[nt][3]));
        }
        pm0 = fmaxf(pm0, __shfl_xor_sync(~0u, pm0, 1));
        pm0 = fmaxf(pm0, __shfl_xor_sync(~0u, pm0, 2));
        pm1 = fmaxf(pm1, __shfl_xor_sync(~0u, pm1, 1));
        pm1 = fmaxf(pm1, __shfl_xor_sync(~0u, pm1, 2));
        const float mn0 = fmaxf(m0, pm0), mn1 = fmaxf(m1, pm1);
        const float cr0 = __expf(m0 - mn0), cr1 = __expf(m1 - mn1);
        m0 = mn0; m1 = mn1;

        float ps0 = 0.f, ps1 = 0.f;
#pragma unroll
        for (int nt = 0; nt < 8; nt++) {
            sf[nt][0] = __expf(sf[nt][0] - mn0);
            sf[nt][1] = __expf(sf[nt][1] - mn0);
            sf[nt][2] = __expf(sf[nt][2] - mn1);
            sf[nt][3] = __expf(sf[nt][3] - mn1);
            ps0 += sf[nt][0] + sf[nt][1];
            ps1 += sf[nt][2] + sf[nt][3];
        }
        ps0 += __shfl_xor_sync(~0u, ps0, 1);
        ps0 += __shfl_xor_sync(~0u, ps0, 2);
        ps1 += __shfl_xor_sync(~0u, ps1, 1);
        ps1 += __shfl_xor_sync(~0u, ps1, 2);
        l0 = l0 * cr0 + ps0;
        l1 = l1 * cr1 + ps1;
#pragma unroll
        for (int nt = 0; nt < 16; nt++) {
            oa[nt][0] *= cr0; oa[nt][1] *= cr0;
            oa[nt][2] *= cr1; oa[nt][3] *= cr1;
        }

        const int krow = (lane & 7) + ((lane >> 3) & 1) * 8;
        const int vcol0 = (lane >> 4) << 3;
#pragma unroll
        for (int kc = 0; kc < 4; kc++) {
            uint32_t pf[4];
            pf[0] = packh2(sf[2 * kc][0],     sf[2 * kc][1]);
            pf[1] = packh2(sf[2 * kc][2],     sf[2 * kc][3]);
            pf[2] = packh2(sf[2 * kc + 1][0], sf[2 * kc + 1][1]);
            pf[3] = packh2(sf[2 * kc + 1][2], sf[2 * kc + 1][3]);
#pragma unroll
            for (int np = 0; np < 8; np++) {
                uint32_t b0, b1, b2, b3;
                const uint32_t addr =
                    vbase + ((kc * 16 + krow) * VPH + vcol0 + np * 16) * 2;
                ldsm_x4_t(b0, b1, b2, b3, addr);
                mma_f16(oa[np * 2],     pf[0], pf[1], pf[2], pf[3], b0, b1);
                mma_f16(oa[np * 2 + 1], pf[0], pf[1], pf[2], pf[3], b2, b3);
            }
        }
    }

    const float i0 = 1.f / l0, i1 = 1.f / l1;
#pragma unroll
    for (int nt = 0; nt < 16; nt++) {
        const int c = nt * 8 + 2 * t;
        __half* o0 = out + (size_t)r0g * (NH * VD) + h * VD + c;
        *(__half2*)o0 = __floats2half2_rn(oa[nt][0] * i0, oa[nt][1] * i0);
        *(__half2*)(o0 + (size_t)8 * (NH * VD)) =
            __floats2half2_rn(oa[nt][2] * i1, oa[nt][3] * i1);
    }
}

// ---------------- launch ----------------
extern "C" void kernel_launch(void* const* d_in, const int* in_sizes, int n_in,
                              void* d_out, int out_size)
{
    const float* hidden = (const float*)d_in[0];
    const float* w_q_a  = (const float*)d_in[1];
    const float* q_a_w  = (const float*)d_in[2];
    const float* w_q_b  = (const float*)d_in[3];
    const float* w_kv_a = (const float*)d_in[4];
    const float* kv_a_w = (const float*)d_in[5];
    const float* w_kv_b = (const float*)d_in[6];
    const float* w_o    = (const float*)d_in[7];
    float* out = (float*)d_out;

    float *qc, *qbuf;
    __half *kv16, *kpe16;
    __half *h16, *wqakva16, *wqb16, *wkvb16, *wo16;
    __half *qlat16, *ckvn16, *attn16;
    cudaGetSymbolAddress((void**)&qc,      g_qc);
    cudaGetSymbolAddress((void**)&qbuf,    g_qbuf);
    cudaGetSymbolAddress((void**)&kv16,    g_kv16);
    cudaGetSymbolAddress((void**)&kpe16,   g_kpe16);
    cudaGetSymbolAddress((void**)&h16,     g_h16);
    cudaGetSymbolAddress((void**)&wqakva16,g_wqakva16);
    cudaGetSymbolAddress((void**)&wqb16,   g_wqb16);
    cudaGetSymbolAddress((void**)&wkvb16,  g_wkvb16);
    cudaGetSymbolAddress((void**)&wo16,    g_wo16);
    cudaGetSymbolAddress((void**)&qlat16,  g_qlat16);
    cudaGetSymbolAddress((void**)&ckvn16,  g_ckvn16);
    cudaGetSymbolAddress((void**)&attn16,  g_attn16);

    cudaFuncSetAttribute(attn_mma, cudaFuncAttributeMaxDynamicSharedMemorySize,
                         ATTN_SMEM);
    cudaFuncSetAttribute(gemm_h<0>, cudaFuncAttributeMaxDynamicSharedMemorySize,
                         GEMM_SMEM);
    cudaFuncSetAttribute(gemm_h<1>, cudaFuncAttributeMaxDynamicSharedMemorySize,
                         GEMM_SMEM);

    // 0: fused converts
    f2h_all_kernel<<<G5, 256>>>(
        hidden, h16, w_q_a, wqakva16, w_kv_a, wqakva16 + (size_t)QLORA * HID,
        w_q_b, wqb16, w_kv_b, wkvb16, w_o, wo16);
    // 1: [qlat | ckv] = hidden @ [wqa | wkva]^T   [2048, 2112]
    gemm_h<0><<<dim3((NC + 127) / 128, S_LEN / 128), 256, GEMM_SMEM>>>(
        h16, wqakva16, qc, S_LEN, NC, HID);
    // 2: fused rmsnorms -> fp16
    rmsnorm2_kernel<<<dim3(S_LEN, 2), 256>>>(qc, q_a_w, kv_a_w, qlat16, ckvn16);
    // 3: q = qlat @ w_q_b^T            [2048, 3072]  <-- profiled slot
    gemm_h<0><<<dim3(NH * QHD / 128, S_LEN / 128), 256, GEMM_SMEM>>>(
        qlat16, wqb16, qbuf, S_LEN, NH * QHD, QLORA);
    // 4: kv = ckvn @ w_kv_b^T          [2048, 4096] fp16 direct
    gemm_h<1><<<dim3(NH * KVD / 128, S_LEN / 128), 256, GEMM_SMEM>>>(
        ckvn16, wkvb16, kv16, S_LEN, NH * KVD, KVLORA);
    // 5: rope
    rope_kernel<<<S_LEN, 544>>>(qbuf, qc, kpe16);
    // 6: attention
    attn_mma<<<dim3(S_LEN / 128, NH), 256, ATTN_SMEM>>>(qbuf, kv16, kpe16, attn16);
    // 7: out = attn @ w_o^T            [2048, 2048]
    gemm_h<0><<<dim3(HID / 128, S_LEN / 128), 256, GEMM_SMEM>>>(
        attn16, wo16, out, S_LEN, HID, HID);
}

// round 16
// speedup vs baseline: 1.0370x; 1.0370x over previous
#include <cuda_runtime.h>
#include <cuda_fp16.h>
#include <math.h>
#include <cstdint>

#define S_LEN  2048
#define HID    2048
#define NH     16
#define QLORA  1536
#define KVLORA 512
#define NOPE   128
#define ROPED  64
#define VD     128
#define QHD    192
#define KVD    256
#define NC     2112                  // QLORA + KVLORA + ROPED

// ---------------- scratch ----------------
__device__ float  g_qc   [S_LEN * NC];
__device__ float  g_qbuf [S_LEN * NH * QHD];
__device__ __half g_kv16 [S_LEN * NH * KVD];
__device__ __half g_kpe16[S_LEN * ROPED];
__device__ __half g_h16     [S_LEN * HID];
__device__ __half g_wqakva16[NC * HID];
__device__ __half g_wqb16   [NH * QHD * QLORA];
__device__ __half g_wkvb16  [NH * KVD * KVLORA];
__device__ __half g_wo16    [HID * NH * VD];
__device__ __half g_qlat16  [S_LEN * QLORA];
__device__ __half g_ckvn16  [S_LEN * KVLORA];
__device__ __half g_attn16  [S_LEN * NH * VD];

// ======================= helpers =======================
__device__ __forceinline__ uint32_t smem_u32(const void* p) {
    uint32_t a;
    asm("{ .reg .u64 t; cvta.to.shared.u64 t, %1; cvt.u32.u64 %0, t; }"
        : "=r"(a) : "l"(p));
    return a;
}
__device__ __forceinline__ uint32_t packh2(float a, float b) {
    __half2 h = __floats2half2_rn(a, b);
    return *(uint32_t*)&h;
}
__device__ __forceinline__ void mma_f16(float* d, uint32_t a0, uint32_t a1,
                                        uint32_t a2, uint32_t a3,
                                        uint32_t b0, uint32_t b1) {
    asm volatile(
        "mma.sync.aligned.m16n8k16.row.col.f32.f16.f16.f32 "
        "{%0,%1,%2,%3}, {%4,%5,%6,%7}, {%8,%9}, {%0,%1,%2,%3};"
        : "+f"(d[0]), "+f"(d[1]), "+f"(d[2]), "+f"(d[3])
        : "r"(a0), "r"(a1), "r"(a2), "r"(a3), "r"(b0), "r"(b1));
}
__device__ __forceinline__ void ldsm_x4_t(uint32_t& r0, uint32_t& r1,
                                          uint32_t& r2, uint32_t& r3,
                                          uint32_t addr) {
    asm volatile(
        "ldmatrix.sync.aligned.m8n8.x4.trans.shared.b16 {%0,%1,%2,%3}, [%4];"
        : "=r"(r0), "=r"(r1), "=r"(r2), "=r"(r3) : "r"(addr));
}

// -------- fused float -> half convert: block-uniform, 4x float4/thread ------
#define G0 1024
#define G1 (G0 + 768)
#define G2 (G1 + 288)
#define G3 (G2 + 1152)
#define G4 (G3 + 512)
#define G5 (G4 + 1024)

__global__ __launch_bounds__(256) void f2h_all_kernel(
    const float* __restrict__ s0, __half* __restrict__ d0,
    const float* __restrict__ s1, __half* __restrict__ d1,
    const float* __restrict__ s2, __half* __restrict__ d2,
    const float* __restrict__ s3, __half* __restrict__ d3,
    const float* __restrict__ s4, __half* __restrict__ d4,
    const float* __restrict__ s5, __half* __restrict__ d5)
{
    const int b = blockIdx.x;
    const float* s; __half* d; int lb;
    if      (b < G0) { s = s0; d = d0; lb = b; }
    else if (b < G1) { s = s1; d = d1; lb = b - G0; }
    else if (b < G2) { s = s2; d = d2; lb = b - G1; }
    else if (b < G3) { s = s3; d = d3; lb = b - G2; }
    else if (b < G4) { s = s4; d = d4; lb = b - G3; }
    else             { s = s5; d = d5; lb = b - G4; }
    const int base = lb * 1024 + threadIdx.x;
#pragma unroll
    for (int k = 0; k < 4; k++) {
        const int j = base + k * 256;
        float4 v = ((const float4*)s)[j];
        uint2 o;
        o.x = packh2(v.x, v.y);
        o.y = packh2(v.z, v.w);
        *(uint2*)(d + 4 * j) = o;
    }
}

// ============ shared GEMM inner machinery (K-tile 64, 2 stages) ============
#define SUBT   4096                    // halves per sub-tile (128x32)
#define STGH   16384                   // halves per stage
#define STGB   32768                   // bytes per stage
#define GEMM_SMEM (2 * STGB)           // 65536 bytes

// ---- generic GEMM (bounds-checked B rows, fp32 out): gemm1 / o_proj ----
__global__ __launch_bounds__(256, 2) void gemm_h(
    const __half* __restrict__ A, const __half* __restrict__ B,
    float* __restrict__ C, int M, int N, int K)
{
    extern __shared__ __half smh[];
    const int tid  = threadIdx.x;
    const int lane = tid & 31;
    const int w    = tid >> 5;
    const int g    = lane >> 2;
    const int t    = lane & 3;
    const int wm   = w & 3;
    const int wn   = w >> 2;
    const int bm   = blockIdx.y * 128;
    const int bn   = blockIdx.x * 128;

    const uint32_t sbase = smem_u32(smh);
    float acc[2][8][4] = {};
    const int NT = K >> 6;

    const int row0 = tid >> 3;
    const int c8   = (tid & 7) * 8;
    const int sub  = (tid & 7) >> 2;
    const int off  = c8 & 31;
    const __half* aS = A + (size_t)(bm + row0) * K + c8;
    const __half* bS = B + (size_t)(bn + row0) * K + c8;
    const size_t rS = (size_t)32 * K;
    int szb[4];
#pragma unroll
    for (int i = 0; i < 4; i++) szb[i] = (bn + row0 + i * 32 < N) ? 16 : 0;
    const uint32_t aD = sbase + (sub * SUBT + row0 * 32 + off) * 2;
    const uint32_t bD = aD + 2 * SUBT * 2;

    auto issue = [&](int kt, uint32_t so) {
        if (kt < NT) {
            const size_t o = (size_t)kt * 64;
#pragma unroll
            for (int i = 0; i < 4; i++) {
                asm volatile("cp.async.ca.shared.global [%0], [%1], 16;"
                             :: "r"(aD + so + i * 2048), "l"(aS + i * rS + o)
                             : "memory");
                asm volatile("cp.async.ca.shared.global [%0], [%1], 16, %2;"
                             :: "r"(bD + so + i * 2048), "l"(bS + i * rS + o),
                                "r"(szb[i]) : "memory");
            }
        }
        asm volatile("cp.async.commit_group;" ::: "memory");
    };

    issue(0, 0);

    const int aOff = wm * 32 * 32 + g * 32 + 8 * t;
    const int bOff = 2 * SUBT + wn * 64 * 32 + g * 32 + 8 * t;

    for (int kt = 0; kt < NT; kt += 2) {
#pragma unroll
        for (int j = 0; j < 2; j++) {
            asm volatile("cp.async.wait_group 0;" ::: "memory");
            __syncthreads();
            issue(kt + j + 1, (uint32_t)(((j + 1) & 1) * STGB));

            const __half* stg = smh + (j & 1) * STGH;
#pragma unroll
            for (int kk = 0; kk < 2; kk++) {
                const __half* Asp = stg + kk * SUBT + aOff;
                const __half* Bsp = stg + kk * SUBT + bOff;

                uint4 a4[4], b4[8];
#pragma unroll
                for (int rr = 0; rr < 4; rr++)
                    a4[rr] = *(const uint4*)(Asp + rr * 8 * 32);
#pragma unroll
                for (int nt = 0; nt < 8; nt++)
                    b4[nt] = *(const uint4*)(Bsp + nt * 8 * 32);

#pragma unroll
                for (int s = 0; s < 2; s++) {
#pragma unroll
                    for (int mt = 0; mt < 2; mt++) {
                        const uint32_t A0 = s ? a4[2 * mt].z     : a4[2 * mt].x;
                        const uint32_t A1 = s ? a4[2 * mt + 1].z : a4[2 * mt + 1].x;
                        const uint32_t A2 = s ? a4[2 * mt].w     : a4[2 * mt].y;
                        const uint32_t A3 = s ? a4[2 * mt + 1].w : a4[2 * mt + 1].y;
#pragma unroll
                        for (int nt = 0; nt < 8; nt++) {
                            const uint32_t B0 = s ? b4[nt].z : b4[nt].x;
                            const uint32_t B1 = s ? b4[nt].w : b4[nt].y;
                            mma_f16(acc[mt][nt], A0, A1, A2, A3, B0, B1);
                        }
                    }
                }
            }
        }
    }

#pragma unroll
    for (int mt = 0; mt < 2; mt++) {
        const int row = bm + wm * 32 + mt * 16 + g;
#pragma unroll
        for (int nt = 0; nt < 8; nt++) {
            const int col = bn + wn * 64 + nt * 8 + 2 * t;
            if (col < N) {
                *(float2*)&C[(size_t)row * N + col] =
                    make_float2(acc[mt][nt][0], acc[mt][nt][1]);
                *(float2*)&C[(size_t)(row + 8) * N + col] =
                    make_float2(acc[mt][nt][2], acc[mt][nt][3]);
            }
        }
    }
}

// ---- merged q-proj + kv-proj GEMM (no bounds checks; N %128 == 0) ----
// blocks [0, 384): q = qlat16 @ wqb^T  [2048x3072], K=1536, fp32 out
// blocks [384,896): kv = ckvn16 @ wkvb^T [2048x4096], K=512, fp16 out
#define P0_TILES 384                   // 24 x 16
__global__ __launch_bounds__(256, 2) void gemm34(
    const __half* __restrict__ A0, const __half* __restrict__ B0,
    float* __restrict__ C0,
    const __half* __restrict__ A1, const __half* __restrict__ B1,
    __half* __restrict__ C1)
{
    extern __shared__ __half smh[];
    const int tid  = threadIdx.x;
    const int lane = tid & 31;
    const int w    = tid >> 5;
    const int g    = lane >> 2;
    const int t    = lane & 3;
    const int wm   = w & 3;
    const int wn   = w >> 2;

    const __half* A; const __half* B;
    int N, K, bm, bn;
    bool halfout;
    {
        int bid = blockIdx.x;
        if (bid < P0_TILES) {
            A = A0; B = B0; N = NH * QHD; K = QLORA; halfout = false;
            bn = (bid % 24) * 128; bm = (bid / 24) * 128;
        } else {
            bid -= P0_TILES;
            A = A1; B = B1; N = NH * KVD; K = KVLORA; halfout = true;
            bn = (bid % 32) * 128; bm = (bid / 32) * 128;
        }
    }

    const uint32_t sbase = smem_u32(smh);
    float acc[2][8][4] = {};
    const int NT = K >> 6;

    const int row0 = tid >> 3;
    const int c8   = (tid & 7) * 8;
    const int sub  = (tid & 7) >> 2;
    const int off  = c8 & 31;
    const __half* aS = A + (size_t)(bm + row0) * K + c8;
    const __half* bS = B + (size_t)(bn + row0) * K + c8;
    const size_t rS = (size_t)32 * K;
    const uint32_t aD = sbase + (sub * SUBT + row0 * 32 + off) * 2;
    const uint32_t bD = aD + 2 * SUBT * 2;

    auto issue = [&](int kt, uint32_t so) {
        if (kt < NT) {
            const size_t o = (size_t)kt * 64;
#pragma unroll
            for (int i = 0; i < 4; i++) {
                asm volatile("cp.async.ca.shared.global [%0], [%1], 16;"
                             :: "r"(aD + so + i * 2048), "l"(aS + i * rS + o)
                             : "memory");
                asm volatile("cp.async.ca.shared.global [%0], [%1], 16;"
                             :: "r"(bD + so + i * 2048), "l"(bS + i * rS + o)
                             : "memory");
            }
        }
        asm volatile("cp.async.commit_group;" ::: "memory");
    };

    issue(0, 0);

    const int aOff = wm * 32 * 32 + g * 32 + 8 * t;
    const int bOff = 2 * SUBT + wn * 64 * 32 + g * 32 + 8 * t;

    for (int kt = 0; kt < NT; kt += 2) {
#pragma unroll
        for (int j = 0; j < 2; j++) {
            asm volatile("cp.async.wait_group 0;" ::: "memory");
            __syncthreads();
            issue(kt + j + 1, (uint32_t)(((j + 1) & 1) * STGB));

            const __half* stg = smh + (j & 1) * STGH;
#pragma unroll
            for (int kk = 0; kk < 2; kk++) {
                const __half* Asp = stg + kk * SUBT + aOff;
                const __half* Bsp = stg + kk * SUBT + bOff;

                uint4 a4[4], b4[8];
#pragma unroll
                for (int rr = 0; rr < 4; rr++)
                    a4[rr] = *(const uint4*)(Asp + rr * 8 * 32);
#pragma unroll
                for (int nt = 0; nt < 8; nt++)
                    b4[nt] = *(const uint4*)(Bsp + nt * 8 * 32);

#pragma unroll
                for (int s = 0; s < 2; s++) {
#pragma unroll
                    for (int mt = 0; mt < 2; mt++) {
                        const uint32_t A0r = s ? a4[2 * mt].z     : a4[2 * mt].x;
                        const uint32_t A1r = s ? a4[2 * mt + 1].z : a4[2 * mt + 1].x;
                        const uint32_t A2r = s ? a4[2 * mt].w     : a4[2 * mt].y;
                        const uint32_t A3r = s ? a4[2 * mt + 1].w : a4[2 * mt + 1].y;
#pragma unroll
                        for (int nt = 0; nt < 8; nt++) {
                            const uint32_t B0r = s ? b4[nt].z : b4[nt].x;
                            const uint32_t B1r = s ? b4[nt].w : b4[nt].y;
                            mma_f16(acc[mt][nt], A0r, A1r, A2r, A3r, B0r, B1r);
                        }
                    }
                }
            }
        }
    }

#pragma unroll
    for (int mt = 0; mt < 2; mt++) {
        const int row = bm + wm * 32 + mt * 16 + g;
#pragma unroll
        for (int nt = 0; nt < 8; nt++) {
            const int col = bn + wn * 64 + nt * 8 + 2 * t;
            if (halfout) {
                *(__half2*)&C1[(size_t)row * N + col] =
                    __floats2half2_rn(acc[mt][nt][0], acc[mt][nt][1]);
                *(__half2*)&C1[(size_t)(row + 8) * N + col] =
                    __floats2half2_rn(acc[mt][nt][2], acc[mt][nt][3]);
            } else {
                *(float2*)&C0[(size_t)row * N + col] =
                    make_float2(acc[mt][nt][0], acc[mt][nt][1]);
                *(float2*)&C0[(size_t)(row + 8) * N + col] =
                    make_float2(acc[mt][nt][2], acc[mt][nt][3]);
            }
        }
    }
}

// ---------------- fused RMSNorm: y==0 -> qlat, y==1 -> ckv ----------------
__global__ __launch_bounds__(256) void rmsnorm2_kernel(
    const float* __restrict__ qc, const float* __restrict__ wq,
    const float* __restrict__ wkv, __half* __restrict__ yq,
    __half* __restrict__ ykv)
{
    const int row = blockIdx.x;
    const float* xr;
    const float* w;
    __half* yr;
    int ncols;
    if (blockIdx.y == 0) {
        xr = qc + (size_t)row * NC;          w = wq;  yr = yq + (size_t)row * QLORA;
        ncols = QLORA;
    } else {
        xr = qc + (size_t)row * NC + QLORA;  w = wkv; yr = ykv + (size_t)row * KVLORA;
        ncols = KVLORA;
    }
    const int n4 = ncols >> 2;

    float ss = 0.f;
    for (int c = threadIdx.x; c < n4; c += 256) {
        float4 v = ((const float4*)xr)[c];
        ss += v.x * v.x + v.y * v.y + v.z * v.z + v.w * v.w;
    }
    __shared__ float red[8];
#pragma unroll
    for (int o = 16; o; o >>= 1) ss += __shfl_xor_sync(~0u, ss, o);
    if ((threadIdx.x & 31) == 0) red[threadIdx.x >> 5] = ss;
    __syncthreads();
    if (threadIdx.x < 32) {
        float v = (threadIdx.x < 8) ? red[threadIdx.x] : 0.f;
#pragma unroll
        for (int o = 4; o; o >>= 1) v += __shfl_xor_sync(~0u, v, o);
        if (threadIdx.x == 0) red[0] = v;
    }
    __syncthreads();
    const float inv = rsqrtf(red[0] / (float)ncols + 1e-6f);
    for (int c = threadIdx.x; c < n4; c += 256) {
        float4 v = ((const float4*)xr)[c];
        float4 wv = ((const float4*)w)[c];
        uint2 o;
        o.x = packh2(v.x * inv * wv.x, v.y * inv * wv.y);
        o.y = packh2(v.z * inv * wv.z, v.w * inv * wv.w);
        *(uint2*)(yr + 4 * c) = o;
    }
}

// ---------------- RoPE (q fp32 in-place; kpe -> fp16) ----------------
__global__ __launch_bounds__(544) void rope_kernel(
    float* __restrict__ q, const float* __restrict__ qc, __half* __restrict__ kpe)
{
    const int s = blockIdx.x;
    const int t = threadIdx.x;
    const int h = t >> 5;
    const int d = t & 31;

    const float f = powf(10000.0f, -(float)d / 32.0f);
    float sn, cs;
    sincosf((float)s * f, &sn, &cs);

    if (h < NH) {
        float* p = q + (size_t)s * (NH * QHD) + h * QHD + NOPE;
        float x1 = p[d], x2 = p[d + 32];
        p[d]      = x1 * cs - x2 * sn;
        p[d + 32] = x2 * cs + x1 * sn;
    } else {
        const float* p = qc + (size_t)s * NC + QLORA + KVLORA;
        float x1 = p[d], x2 = p[d + 32];
        kpe[s * ROPED + d]      = __float2half_rn(x1 * cs - x2 * sn);
        kpe[s * ROPED + d + 32] = __float2half_rn(x2 * cs + x1 * sn);
    }
}

// ======== Flash attention FA2-style: BQ=128, 3-stage KV, 1 sync/iter ========
#define SKH 224
#define VPH 136
#define STG_B 46080
#define ATTN_SMEM (3 * STG_B)

__global__ __launch_bounds__(256) void attn_mma(
    const float* __restrict__ q, const __half* __restrict__ kv16,
    const __half* __restrict__ kpe16, __half* __restrict__ out)
{
    extern __shared__ char smc[];
    const int tid = threadIdx.x, lane = tid & 31, wid = tid >> 5;
    const int g = lane >> 2, t = lane & 3;
    const int qb = (int)gridDim.x - 1 - (int)blockIdx.x;
    const int h  = blockIdx.y;
    const uint32_t sbase = smem_u32(smc);

    uint32_t qf[12][4];
    {
        const float sc = 0.07216878364870323f;
        const float* Qg0 =
            q + (size_t)(qb * 128 + wid * 16 + g) * (NH * QHD) + h * QHD;
        const float* Qg1 = Qg0 + (size_t)8 * (NH * QHD);
#pragma unroll
        for (int m = 0; m < 12; m++) {
            const int kk = 32 * (m >> 1) + 8 * t + 4 * (m & 1);
            qf[m][0] = packh2(sc * Qg0[kk],     sc * Qg0[kk + 1]);
            qf[m][1] = packh2(sc * Qg1[kk],     sc * Qg1[kk + 1]);
            qf[m][2] = packh2(sc * Qg0[kk + 2], sc * Qg0[kk + 3]);
            qf[m][3] = packh2(sc * Qg1[kk + 2], sc * Qg1[kk + 3]);
        }
    }

    float oa[16][4] = {};
    float m0 = -1e30f, m1 = -1e30f, l0 = 0.f, l1 = 0.f;
    const int nkb = 2 * qb + 2;

    auto fill = [&](int kb) {
        if (kb < nkb) {
            const uint32_t kd = sbase + (kb % 3) * STG_B;
            const uint32_t vd = kd + 28672;
#pragma unroll
            for (int i = 0; i < 6; i++) {
                int idx = tid + i * 256;
                int r = idx / 24, c8 = (idx % 24) * 8;
                const __half* src = (c8 < 128)
                    ? (kv16 + (size_t)(kb * 64 + r) * (NH * KVD) + h * KVD + c8)
                    : (kpe16 + (size_t)(kb * 64 + r) * ROPED + (c8 - 128));
                uint32_t d = kd + (r * SKH + c8) * 2;
                asm volatile("cp.async.ca.shared.global [%0], [%1], 16;"
                             :: "r"(d), "l"(src) : "memory");
            }
            const __half* vsrc =
                kv16 + (size_t)(kb * 64) * (NH * KVD) + h * KVD + NOPE;
#pragma unroll
            for (int i = 0; i < 4; i++) {
                int idx = tid + i * 256;
                int r = idx >> 4, c8 = (idx & 15) * 8;
                uint32_t d = vd + (r * VPH + c8) * 2;
                asm volatile("cp.async.ca.shared.global [%0], [%1], 16;"
                             :: "r"(d), "l"(vsrc + (size_t)r * (NH * KVD) + c8)
                             : "memory");
            }
        }
        asm volatile("cp.async.commit_group;" ::: "memory");
    };

    fill(0); fill(1);

    const int r0g = qb * 128 + wid * 16 + g;
    const int r1g = r0g + 8;

    for (int kb = 0; kb < nkb; kb++) {
        asm volatile("cp.async.wait_group 1;" ::: "memory");
        __syncthreads();
        fill(kb + 2);

        const __half* Ks = (const __half*)(smc + (kb % 3) * STG_B);
        const uint32_t vbase = sbase + (kb % 3) * STG_B + 28672;

        float sf[8][4] = {};
#pragma unroll
        for (int s2 = 0; s2 < 6; s2++) {
            const int co = s2 * 32 + 8 * t;
            uint4 k4[8];
#pragma unroll
            for (int nt = 0; nt < 8; nt++)
                k4[nt] = *(const uint4*)(Ks + (nt * 8 + g) * SKH + co);
#pragma unroll
            for (int nt = 0; nt < 8; nt++) {
                mma_f16(sf[nt], qf[2 * s2][0], qf[2 * s2][1],
                        qf[2 * s2][2], qf[2 * s2][3], k4[nt].x, k4[nt].y);
                mma_f16(sf[nt], qf[2 * s2 + 1][0], qf[2 * s2 + 1][1],
                        qf[2 * s2 + 1][2], qf[2 * s2 + 1][3], k4[nt].z, k4[nt].w);
            }
        }

        float pm0 = -1e30f, pm1 = -1e30f;
        const bool diag = (kb >= 2 * qb);
#pragma unroll
        for (int nt = 0; nt < 8; nt++) {
            const int c = kb * 64 + nt * 8 + 2 * t;
            if (diag) {
                if (c     > r0g) sf[nt][0] = -1e30f;
                if (c + 1 > r0g) sf[nt][1] = -1e30f;
                if (c     > r1g) sf[nt][2] = -1e30f;
                if (c + 1 > r1g) sf[nt][3] = -1e30f;
            }
            pm0 = fmaxf(pm0, fmaxf(sf[nt][0], sf[nt][1]));
            pm1 = fmaxf(pm1, fmaxf(sf[nt][2], sf[nt][3]));
        }
        pm0 = fmaxf(pm0, __shfl_xor_sync(~0u, pm0, 1));
        pm0 = fmaxf(pm0, __shfl_xor_sync(~0u, pm0, 2));
        pm1 = fmaxf(pm1, __shfl_xor_sync(~0u, pm1, 1));
        pm1 = fmaxf(pm1, __shfl_xor_sync(~0u, pm1, 2));
        const float mn0 = fmaxf(m0, pm0), mn1 = fmaxf(m1, pm1);
        const float cr0 = __expf(m0 - mn0), cr1 = __expf(m1 - mn1);
        m0 = mn0; m1 = mn1;

        float ps0 = 0.f, ps1 = 0.f;
#pragma unroll
        for (int nt = 0; nt < 8; nt++) {
            sf[nt][0] = __expf(sf[nt][0] - mn0);
            sf[nt][1] = __expf(sf[nt][1] - mn0);
            sf[nt][2] = __expf(sf[nt][2] - mn1);
            sf[nt][3] = __expf(sf[nt][3] - mn1);
            ps0 += sf[nt][0] + sf[nt][1];
            ps1 += sf[nt][2] + sf[nt][3];
        }
        ps0 += __shfl_xor_sync(~0u, ps0, 1);
        ps0 += __shfl_xor_sync(~0u, ps0, 2);
        ps1 += __shfl_xor_sync(~0u, ps1, 1);
        ps1 += __shfl_xor_sync(~0u, ps1, 2);
        l0 = l0 * cr0 + ps0;
        l1 = l1 * cr1 + ps1;
#pragma unroll
        for (int nt = 0; nt < 16; nt++) {
            oa[nt][0] *= cr0; oa[nt][1] *= cr0;
            oa[nt][2] *= cr1; oa[nt][3] *= cr1;
        }

        const int krow = (lane & 7) + ((lane >> 3) & 1) * 8;
        const int vcol0 = (lane >> 4) << 3;
#pragma unroll
        for (int kc = 0; kc < 4; kc++) {
            uint32_t pf[4];
            pf[0] = packh2(sf[2 * kc][0],     sf[2 * kc][1]);
            pf[1] = packh2(sf[2 * kc][2],     sf[2 * kc][3]);
            pf[2] = packh2(sf[2 * kc + 1][0], sf[2 * kc + 1][1]);
            pf[3] = packh2(sf[2 * kc + 1][2], sf[2 * kc + 1][3]);
#pragma unroll
            for (int np = 0; np < 8; np++) {
                uint32_t b0, b1, b2, b3;
                const uint32_t addr =
                    vbase + ((kc * 16 + krow) * VPH + vcol0 + np * 16) * 2;
                ldsm_x4_t(b0, b1, b2, b3, addr);
                mma_f16(oa[np * 2],     pf[0], pf[1], pf[2], pf[3], b0, b1);
                mma_f16(oa[np * 2 + 1], pf[0], pf[1], pf[2], pf[3], b2, b3);
            }
        }
    }

    const float i0 = 1.f / l0, i1 = 1.f / l1;
#pragma unroll
    for (int nt = 0; nt < 16; nt++) {
        const int c = nt * 8 + 2 * t;
        __half* o0 = out + (size_t)r0g * (NH * VD) + h * VD + c;
        *(__half2*)o0 = __floats2half2_rn(oa[nt][0] * i0, oa[nt][1] * i0);
        *(__half2*)(o0 + (size_t)8 * (NH * VD)) =
            __floats2half2_rn(oa[nt][2] * i1, oa[nt][3] * i1);
    }
}

// ---------------- launch ----------------
extern "C" void kernel_launch(void* const* d_in, const int* in_sizes, int n_in,
                              void* d_out, int out_size)
{
    const float* hidden = (const float*)d_in[0];
    const float* w_q_a  = (const float*)d_in[1];
    const float* q_a_w  = (const float*)d_in[2];
    const float* w_q_b  = (const float*)d_in[3];
    const float* w_kv_a = (const float*)d_in[4];
    const float* kv_a_w = (const float*)d_in[5];
    const float* w_kv_b = (const float*)d_in[6];
    const float* w_o    = (const float*)d_in[7];
    float* out = (float*)d_out;

    float *qc, *qbuf;
    __half *kv16, *kpe16;
    __half *h16, *wqakva16, *wqb16, *wkvb16, *wo16;
    __half *qlat16, *ckvn16, *attn16;
    cudaGetSymbolAddress((void**)&qc,      g_qc);
    cudaGetSymbolAddress((void**)&qbuf,    g_qbuf);
    cudaGetSymbolAddress((void**)&kv16,    g_kv16);
    cudaGetSymbolAddress((void**)&kpe16,   g_kpe16);
    cudaGetSymbolAddress((void**)&h16,     g_h16);
    cudaGetSymbolAddress((void**)&wqakva16,g_wqakva16);
    cudaGetSymbolAddress((void**)&wqb16,   g_wqb16);
    cudaGetSymbolAddress((void**)&wkvb16,  g_wkvb16);
    cudaGetSymbolAddress((void**)&wo16,    g_wo16);
    cudaGetSymbolAddress((void**)&qlat16,  g_qlat16);
    cudaGetSymbolAddress((void**)&ckvn16,  g_ckvn16);
    cudaGetSymbolAddress((void**)&attn16,  g_attn16);

    cudaFuncSetAttribute(attn_mma, cudaFuncAttributeMaxDynamicSharedMemorySize,
                         ATTN_SMEM);
    cudaFuncSetAttribute(gemm_h, cudaFuncAttributeMaxDynamicSharedMemorySize,
                         GEMM_SMEM);
    cudaFuncSetAttribute(gemm34, cudaFuncAttributeMaxDynamicSharedMemorySize,
                         GEMM_SMEM);

    // 0: fused converts
    f2h_all_kernel<<<G5, 256>>>(
        hidden, h16, w_q_a, wqakva16, w_kv_a, wqakva16 + (size_t)QLORA * HID,
        w_q_b, wqb16, w_kv_b, wkvb16, w_o, wo16);
    // 1: [qlat | ckv] = hidden @ [wqa | wkva]^T   [2048, 2112]
    gemm_h<<<dim3((NC + 127) / 128, S_LEN / 128), 256, GEMM_SMEM>>>(
        h16, wqakva16, qc, S_LEN, NC, HID);
    // 2: fused rmsnorms -> fp16
    rmsnorm2_kernel<<<dim3(S_LEN, 2), 256>>>(qc, q_a_w, kv_a_w, qlat16, ckvn16);
    // 3: MERGED q-proj + kv-proj (896 CTAs)   <-- profiled slot
    gemm34<<<896, 256, GEMM_SMEM>>>(qlat16, wqb16, qbuf, ckvn16, wkvb16, kv16);
    // 4: rope
    rope_kernel<<<S_LEN, 544>>>(qbuf, qc, kpe16);
    // 5: attention
    attn_mma<<<dim3(S_LEN / 128, NH), 256, ATTN_SMEM>>>(qbuf, kv16, kpe16, attn16);
    // 6: out = attn @ w_o^T            [2048, 2048]
    gemm_h<<<dim3(HID / 128, S_LEN / 128), 256, GEMM_SMEM>>>(
        attn16, wo16, out, S_LEN, HID, HID);
}

// round 17
// speedup vs baseline: 1.0468x; 1.0095x over previous
#include <cuda_runtime.h>
#include <cuda_fp16.h>
#include <math.h>
#include <cstdint>

#define S_LEN  2048
#define HID    2048
#define NH     16
#define QLORA  1536
#define KVLORA 512
#define NOPE   128
#define ROPED  64
#define VD     128
#define QHD    192
#define KVD    256
#define NC     2112                  // QLORA + KVLORA + ROPED

// ---------------- scratch ----------------
__device__ float  g_qc   [S_LEN * NC];
__device__ __half g_q16  [S_LEN * NH * QHD];    // pre-scaled fp16 q
__device__ __half g_kv16 [S_LEN * NH * KVD];
__device__ __half g_kpe16[S_LEN * ROPED];
__device__ __half g_h16     [S_LEN * HID];
__device__ __half g_wqakva16[NC * HID];
__device__ __half g_wqb16   [NH * QHD * QLORA];
__device__ __half g_wkvb16  [NH * KVD * KVLORA];
__device__ __half g_wo16    [HID * NH * VD];
__device__ __half g_qlat16  [S_LEN * QLORA];
__device__ __half g_ckvn16  [S_LEN * KVLORA];
__device__ __half g_attn16  [S_LEN * NH * VD];

// ======================= helpers =======================
__device__ __forceinline__ uint32_t smem_u32(const void* p) {
    uint32_t a;
    asm("{ .reg .u64 t; cvta.to.shared.u64 t, %1; cvt.u32.u64 %0, t; }"
        : "=r"(a) : "l"(p));
    return a;
}
__device__ __forceinline__ uint32_t packh2(float a, float b) {
    __half2 h = __floats2half2_rn(a, b);
    return *(uint32_t*)&h;
}
__device__ __forceinline__ void mma_f16(float* d, uint32_t a0, uint32_t a1,
                                        uint32_t a2, uint32_t a3,
                                        uint32_t b0, uint32_t b1) {
    asm volatile(
        "mma.sync.aligned.m16n8k16.row.col.f32.f16.f16.f32 "
        "{%0,%1,%2,%3}, {%4,%5,%6,%7}, {%8,%9}, {%0,%1,%2,%3};"
        : "+f"(d[0]), "+f"(d[1]), "+f"(d[2]), "+f"(d[3])
        : "r"(a0), "r"(a1), "r"(a2), "r"(a3), "r"(b0), "r"(b1));
}
__device__ __forceinline__ void ldsm_x4_t(uint32_t& r0, uint32_t& r1,
                                          uint32_t& r2, uint32_t& r3,
                                          uint32_t addr) {
    asm volatile(
        "ldmatrix.sync.aligned.m8n8.x4.trans.shared.b16 {%0,%1,%2,%3}, [%4];"
        : "=r"(r0), "=r"(r1), "=r"(r2), "=r"(r3) : "r"(addr));
}

// -------- fused float -> half convert: block-uniform, 4x float4/thread ------
#define G0 1024
#define G1 (G0 + 768)
#define G2 (G1 + 288)
#define G3 (G2 + 1152)
#define G4 (G3 + 512)
#define G5 (G4 + 1024)

__global__ __launch_bounds__(256) void f2h_all_kernel(
    const float* __restrict__ s0, __half* __restrict__ d0,
    const float* __restrict__ s1, __half* __restrict__ d1,
    const float* __restrict__ s2, __half* __restrict__ d2,
    const float* __restrict__ s3, __half* __restrict__ d3,
    const float* __restrict__ s4, __half* __restrict__ d4,
    const float* __restrict__ s5, __half* __restrict__ d5)
{
    const int b = blockIdx.x;
    const float* s; __half* d; int lb;
    if      (b < G0) { s = s0; d = d0; lb = b; }
    else if (b < G1) { s = s1; d = d1; lb = b - G0; }
    else if (b < G2) { s = s2; d = d2; lb = b - G1; }
    else if (b < G3) { s = s3; d = d3; lb = b - G2; }
    else if (b < G4) { s = s4; d = d4; lb = b - G3; }
    else             { s = s5; d = d5; lb = b - G4; }
    const int base = lb * 1024 + threadIdx.x;
#pragma unroll
    for (int k = 0; k < 4; k++) {
        const int j = base + k * 256;
        float4 v = ((const float4*)s)[j];
        uint2 o;
        o.x = packh2(v.x, v.y);
        o.y = packh2(v.z, v.w);
        *(uint2*)(d + 4 * j) = o;
    }
}

// ============ shared GEMM inner machinery (K-tile 64, 2 stages) ============
#define SUBT   4096
#define STGH   16384
#define STGB   32768
#define GEMM_SMEM (2 * STGB)

// ---- generic GEMM (bounds-checked B rows, fp32 out): gemm1 / o_proj ----
__global__ __launch_bounds__(256, 2) void gemm_h(
    const __half* __restrict__ A, const __half* __restrict__ B,
    float* __restrict__ C, int M, int N, int K)
{
    extern __shared__ __half smh[];
    const int tid  = threadIdx.x;
    const int lane = tid & 31;
    const int w    = tid >> 5;
    const int g    = lane >> 2;
    const int t    = lane & 3;
    const int wm   = w & 3;
    const int wn   = w >> 2;
    const int bm   = blockIdx.y * 128;
    const int bn   = blockIdx.x * 128;

    const uint32_t sbase = smem_u32(smh);
    float acc[2][8][4] = {};
    const int NT = K >> 6;

    const int row0 = tid >> 3;
    const int c8   = (tid & 7) * 8;
    const int sub  = (tid & 7) >> 2;
    const int off  = c8 & 31;
    const __half* aS = A + (size_t)(bm + row0) * K + c8;
    const __half* bS = B + (size_t)(bn + row0) * K + c8;
    const size_t rS = (size_t)32 * K;
    int szb[4];
#pragma unroll
    for (int i = 0; i < 4; i++) szb[i] = (bn + row0 + i * 32 < N) ? 16 : 0;
    const uint32_t aD = sbase + (sub * SUBT + row0 * 32 + off) * 2;
    const uint32_t bD = aD + 2 * SUBT * 2;

    auto issue = [&](int kt, uint32_t so) {
        if (kt < NT) {
            const size_t o = (size_t)kt * 64;
#pragma unroll
            for (int i = 0; i < 4; i++) {
                asm volatile("cp.async.ca.shared.global [%0], [%1], 16;"
                             :: "r"(aD + so + i * 2048), "l"(aS + i * rS + o)
                             : "memory");
                asm volatile("cp.async.ca.shared.global [%0], [%1], 16, %2;"
                             :: "r"(bD + so + i * 2048), "l"(bS + i * rS + o),
                                "r"(szb[i]) : "memory");
            }
        }
        asm volatile("cp.async.commit_group;" ::: "memory");
    };

    issue(0, 0);

    const int aOff = wm * 32 * 32 + g * 32 + 8 * t;
    const int bOff = 2 * SUBT + wn * 64 * 32 + g * 32 + 8 * t;

    for (int kt = 0; kt < NT; kt += 2) {
#pragma unroll
        for (int j = 0; j < 2; j++) {
            asm volatile("cp.async.wait_group 0;" ::: "memory");
            __syncthreads();
            issue(kt + j + 1, (uint32_t)(((j + 1) & 1) * STGB));

            const __half* stg = smh + (j & 1) * STGH;
#pragma unroll
            for (int kk = 0; kk < 2; kk++) {
                const __half* Asp = stg + kk * SUBT + aOff;
                const __half* Bsp = stg + kk * SUBT + bOff;

                uint4 a4[4], b4[8];
#pragma unroll
                for (int rr = 0; rr < 4; rr++)
                    a4[rr] = *(const uint4*)(Asp + rr * 8 * 32);
#pragma unroll
                for (int nt = 0; nt < 8; nt++)
                    b4[nt] = *(const uint4*)(Bsp + nt * 8 * 32);

#pragma unroll
                for (int s = 0; s < 2; s++) {
#pragma unroll
                    for (int mt = 0; mt < 2; mt++) {
                        const uint32_t A0 = s ? a4[2 * mt].z     : a4[2 * mt].x;
                        const uint32_t A1 = s ? a4[2 * mt + 1].z : a4[2 * mt + 1].x;
                        const uint32_t A2 = s ? a4[2 * mt].w     : a4[2 * mt].y;
                        const uint32_t A3 = s ? a4[2 * mt + 1].w : a4[2 * mt + 1].y;
#pragma unroll
                        for (int nt = 0; nt < 8; nt++) {
                            const uint32_t B0 = s ? b4[nt].z : b4[nt].x;
                            const uint32_t B1 = s ? b4[nt].w : b4[nt].y;
                            mma_f16(acc[mt][nt], A0, A1, A2, A3, B0, B1);
                        }
                    }
                }
            }
        }
    }

#pragma unroll
    for (int mt = 0; mt < 2; mt++) {
        const int row = bm + wm * 32 + mt * 16 + g;
#pragma unroll
        for (int nt = 0; nt < 8; nt++) {
            const int col = bn + wn * 64 + nt * 8 + 2 * t;
            if (col < N) {
                *(float2*)&C[(size_t)row * N + col] =
                    make_float2(acc[mt][nt][0], acc[mt][nt][1]);
                *(float2*)&C[(size_t)(row + 8) * N + col] =
                    make_float2(acc[mt][nt][2], acc[mt][nt][3]);
            }
        }
    }
}

// ---- merged q-proj + kv-proj GEMM (no bounds checks; both fp16 out) ----
// blocks [0, 384): q16 = (qlat16 @ wqb^T) * scale  [2048x3072], K=1536
// blocks [384,896): kv16 = ckvn16 @ wkvb^T [2048x4096], K=512
#define P0_TILES 384
__global__ __launch_bounds__(256, 2) void gemm34(
    const __half* __restrict__ A0, const __half* __restrict__ B0,
    __half* __restrict__ C0,
    const __half* __restrict__ A1, const __half* __restrict__ B1,
    __half* __restrict__ C1)
{
    extern __shared__ __half smh[];
    const int tid  = threadIdx.x;
    const int lane = tid & 31;
    const int w    = tid >> 5;
    const int g    = lane >> 2;
    const int t    = lane & 3;
    const int wm   = w & 3;
    const int wn   = w >> 2;

    const __half* A; const __half* B; __half* C;
    int N, K, bm, bn;
    float scl;
    {
        int bid = blockIdx.x;
        if (bid < P0_TILES) {
            A = A0; B = B0; C = C0; N = NH * QHD; K = QLORA;
            scl = 0.07216878364870323f;
            bn = (bid % 24) * 128; bm = (bid / 24) * 128;
        } else {
            bid -= P0_TILES;
            A = A1; B = B1; C = C1; N = NH * KVD; K = KVLORA;
            scl = 1.0f;
            bn = (bid % 32) * 128; bm = (bid / 32) * 128;
        }
    }

    const uint32_t sbase = smem_u32(smh);
    float acc[2][8][4] = {};
    const int NT = K >> 6;

    const int row0 = tid >> 3;
    const int c8   = (tid & 7) * 8;
    const int sub  = (tid & 7) >> 2;
    const int off  = c8 & 31;
    const __half* aS = A + (size_t)(bm + row0) * K + c8;
    const __half* bS = B + (size_t)(bn + row0) * K + c8;
    const size_t rS = (size_t)32 * K;
    const uint32_t aD = sbase + (sub * SUBT + row0 * 32 + off) * 2;
    const uint32_t bD = aD + 2 * SUBT * 2;

    auto issue = [&](int kt, uint32_t so) {
        if (kt < NT) {
            const size_t o = (size_t)kt * 64;
#pragma unroll
            for (int i = 0; i < 4; i++) {
                asm volatile("cp.async.ca.shared.global [%0], [%1], 16;"
                             :: "r"(aD + so + i * 2048), "l"(aS + i * rS + o)
                             : "memory");
                asm volatile("cp.async.ca.shared.global [%0], [%1], 16;"
                             :: "r"(bD + so + i * 2048), "l"(bS + i * rS + o)
                             : "memory");
            }
        }
        asm volatile("cp.async.commit_group;" ::: "memory");
    };

    issue(0, 0);

    const int aOff = wm * 32 * 32 + g * 32 + 8 * t;
    const int bOff = 2 * SUBT + wn * 64 * 32 + g * 32 + 8 * t;

    for (int kt = 0; kt < NT; kt += 2) {
#pragma unroll
        for (int j = 0; j < 2; j++) {
            asm volatile("cp.async.wait_group 0;" ::: "memory");
            __syncthreads();
            issue(kt + j + 1, (uint32_t)(((j + 1) & 1) * STGB));

            const __half* stg = smh + (j & 1) * STGH;
#pragma unroll
            for (int kk = 0; kk < 2; kk++) {
                const __half* Asp = stg + kk * SUBT + aOff;
                const __half* Bsp = stg + kk * SUBT + bOff;

                uint4 a4[4], b4[8];
#pragma unroll
                for (int rr = 0; rr < 4; rr++)
                    a4[rr] = *(const uint4*)(Asp + rr * 8 * 32);
#pragma unroll
                for (int nt = 0; nt < 8; nt++)
                    b4[nt] = *(const uint4*)(Bsp + nt * 8 * 32);

#pragma unroll
                for (int s = 0; s < 2; s++) {
#pragma unroll
                    for (int mt = 0; mt < 2; mt++) {
                        const uint32_t A0r = s ? a4[2 * mt].z     : a4[2 * mt].x;
                        const uint32_t A1r = s ? a4[2 * mt + 1].z : a4[2 * mt + 1].x;
                        const uint32_t A2r = s ? a4[2 * mt].w     : a4[2 * mt].y;
                        const uint32_t A3r = s ? a4[2 * mt + 1].w : a4[2 * mt + 1].y;
#pragma unroll
                        for (int nt = 0; nt < 8; nt++) {
                            const uint32_t B0r = s ? b4[nt].z : b4[nt].x;
                            const uint32_t B1r = s ? b4[nt].w : b4[nt].y;
                            mma_f16(acc[mt][nt], A0r, A1r, A2r, A3r, B0r, B1r);
                        }
                    }
                }
            }
        }
    }

#pragma unroll
    for (int mt = 0; mt < 2; mt++) {
        const int row = bm + wm * 32 + mt * 16 + g;
#pragma unroll
        for (int nt = 0; nt < 8; nt++) {
            const int col = bn + wn * 64 + nt * 8 + 2 * t;
            *(__half2*)&C[(size_t)row * N + col] =
                __floats2half2_rn(acc[mt][nt][0] * scl, acc[mt][nt][1] * scl);
            *(__half2*)&C[(size_t)(row + 8) * N + col] =
                __floats2half2_rn(acc[mt][nt][2] * scl, acc[mt][nt][3] * scl);
        }
    }
}

// ---------------- fused RMSNorm: y==0 -> qlat, y==1 -> ckv ----------------
__global__ __launch_bounds__(256) void rmsnorm2_kernel(
    const float* __restrict__ qc, const float* __restrict__ wq,
    const float* __restrict__ wkv, __half* __restrict__ yq,
    __half* __restrict__ ykv)
{
    const int row = blockIdx.x;
    const float* xr;
    const float* w;
    __half* yr;
    int ncols;
    if (blockIdx.y == 0) {
        xr = qc + (size_t)row * NC;          w = wq;  yr = yq + (size_t)row * QLORA;
        ncols = QLORA;
    } else {
        xr = qc + (size_t)row * NC + QLORA;  w = wkv; yr = ykv + (size_t)row * KVLORA;
        ncols = KVLORA;
    }
    const int n4 = ncols >> 2;

    float ss = 0.f;
    for (int c = threadIdx.x; c < n4; c += 256) {
        float4 v = ((const float4*)xr)[c];
        ss += v.x * v.x + v.y * v.y + v.z * v.z + v.w * v.w;
    }
    __shared__ float red[8];
#pragma unroll
    for (int o = 16; o; o >>= 1) ss += __shfl_xor_sync(~0u, ss, o);
    if ((threadIdx.x & 31) == 0) red[threadIdx.x >> 5] = ss;
    __syncthreads();
    if (threadIdx.x < 32) {
        float v = (threadIdx.x < 8) ? red[threadIdx.x] : 0.f;
#pragma unroll
        for (int o = 4; o; o >>= 1) v += __shfl_xor_sync(~0u, v, o);
        if (threadIdx.x == 0) red[0] = v;
    }
    __syncthreads();
    const float inv = rsqrtf(red[0] / (float)ncols + 1e-6f);
    for (int c = threadIdx.x; c < n4; c += 256) {
        float4 v = ((const float4*)xr)[c];
        float4 wv = ((const float4*)w)[c];
        uint2 o;
        o.x = packh2(v.x * inv * wv.x, v.y * inv * wv.y);
        o.y = packh2(v.z * inv * wv.z, v.w * inv * wv.w);
        *(uint2*)(yr + 4 * c) = o;
    }
}

// ---------------- RoPE (q fp16 in-place; kpe -> fp16) ----------------
__global__ __launch_bounds__(544) void rope_kernel(
    __half* __restrict__ q, const float* __restrict__ qc,
    __half* __restrict__ kpe)
{
    const int s = blockIdx.x;
    const int t = threadIdx.x;
    const int h = t >> 5;
    const int d = t & 31;

    const float f = powf(10000.0f, -(float)d / 32.0f);
    float sn, cs;
    sincosf((float)s * f, &sn, &cs);

    if (h < NH) {
        __half* p = q + (size_t)s * (NH * QHD) + h * QHD + NOPE;
        float x1 = __half2float(p[d]), x2 = __half2float(p[d + 32]);
        p[d]      = __float2half_rn(x1 * cs - x2 * sn);
        p[d + 32] = __float2half_rn(x2 * cs + x1 * sn);
    } else {
        const float* p = qc + (size_t)s * NC + QLORA + KVLORA;
        float x1 = p[d], x2 = p[d + 32];
        kpe[s * ROPED + d]      = __float2half_rn(x1 * cs - x2 * sn);
        kpe[s * ROPED + d + 32] = __float2half_rn(x2 * cs + x1 * sn);
    }
}

// ======== Flash attention FA2-style: BQ=128, 3-stage KV, 1 sync/iter ========
#define SKH 224
#define VPH 136
#define STG_B 46080
#define ATTN_SMEM (3 * STG_B)

__global__ __launch_bounds__(256) void attn_mma(
    const __half* __restrict__ q, const __half* __restrict__ kv16,
    const __half* __restrict__ kpe16, __half* __restrict__ out)
{
    extern __shared__ char smc[];
    const int tid = threadIdx.x, lane = tid & 31, wid = tid >> 5;
    const int g = lane >> 2, t = lane & 3;
    const int qb = (int)gridDim.x - 1 - (int)blockIdx.x;
    const int h  = blockIdx.y;
    const uint32_t sbase = smem_u32(smc);

    // Q fragments: q16 is pre-scaled fp16; k-permuted pairs are contiguous
    uint32_t qf[12][4];
    {
        const __half* Qg0 =
            q + (size_t)(qb * 128 + wid * 16 + g) * (NH * QHD) + h * QHD;
        const __half* Qg1 = Qg0 + (size_t)8 * (NH * QHD);
#pragma unroll
        for (int m = 0; m < 12; m++) {
            const int kk = 32 * (m >> 1) + 8 * t + 4 * (m & 1);
            qf[m][0] = *(const uint32_t*)(Qg0 + kk);
            qf[m][1] = *(const uint32_t*)(Qg1 + kk);
            qf[m][2] = *(const uint32_t*)(Qg0 + kk + 2);
            qf[m][3] = *(const uint32_t*)(Qg1 + kk + 2);
        }
    }

    float oa[16][4] = {};
    float m0 = -1e30f, m1 = -1e30f, l0 = 0.f, l1 = 0.f;
    const int nkb = 2 * qb + 2;

    auto fill = [&](int kb) {
        if (kb < nkb) {
            const uint32_t kd = sbase + (kb % 3) * STG_B;
            const uint32_t vd = kd + 28672;
#pragma unroll
            for (int i = 0; i < 6; i++) {
                int idx = tid + i * 256;
                int r = idx / 24, c8 = (idx % 24) * 8;
                const __half* src = (c8 < 128)
                    ? (kv16 + (size_t)(kb * 64 + r) * (NH * KVD) + h * KVD + c8)
                    : (kpe16 + (size_t)(kb * 64 + r) * ROPED + (c8 - 128));
                uint32_t d = kd + (r * SKH + c8) * 2;
                asm volatile("cp.async.ca.shared.global [%0], [%1], 16;"
                             :: "r"(d), "l"(src) : "memory");
            }
            const __half* vsrc =
                kv16 + (size_t)(kb * 64) * (NH * KVD) + h * KVD + NOPE;
#pragma unroll
            for (int i = 0; i < 4; i++) {
                int idx = tid + i * 256;
                int r = idx >> 4, c8 = (idx & 15) * 8;
                uint32_t d = vd + (r * VPH + c8) * 2;
                asm volatile("cp.async.ca.shared.global [%0], [%1], 16;"
                             :: "r"(d), "l"(vsrc + (size_t)r * (NH * KVD) + c8)
                             : "memory");
            }
        }
        asm volatile("cp.async.commit_group;" ::: "memory");
    };

    fill(0); fill(1);

    const int r0g = qb * 128 + wid * 16 + g;
    const int r1g = r0g + 8;

    for (int kb = 0; kb < nkb; kb++) {
        asm volatile("cp.async.wait_group 1;" ::: "memory");
        __syncthreads();
        fill(kb + 2);

        const __half* Ks = (const __half*)(smc + (kb % 3) * STG_B);
        const uint32_t vbase = sbase + (kb % 3) * STG_B + 28672;

        float sf[8][4] = {};
#pragma unroll
        for (int s2 = 0; s2 < 6; s2++) {
            const int co = s2 * 32 + 8 * t;
            uint4 k4[8];
#pragma unroll
            for (int nt = 0; nt < 8; nt++)
                k4[nt] = *(const uint4*)(Ks + (nt * 8 + g) * SKH + co);
#pragma unroll
            for (int nt = 0; nt < 8; nt++) {
                mma_f16(sf[nt], qf[2 * s2][0], qf[2 * s2][1],
                        qf[2 * s2][2], qf[2 * s2][3], k4[nt].x, k4[nt].y);
                mma_f16(sf[nt], qf[2 * s2 + 1][0], qf[2 * s2 + 1][1],
                        qf[2 * s2 + 1][2], qf[2 * s2 + 1][3], k4[nt].z, k4[nt].w);
            }
        }

        float pm0 = -1e30f, pm1 = -1e30f;
        const bool diag = (kb >= 2 * qb);
#pragma unroll
        for (int nt = 0; nt < 8; nt++) {
            const int c = kb * 64 + nt * 8 + 2 * t;
            if (diag) {
                if (c     > r0g) sf[nt][0] = -1e30f;
                if (c + 1 > r0g) sf[nt][1] = -1e30f;
                if (c     > r1g) sf[nt][2] = -1e30f;
                if (c + 1 > r1g) sf[nt][3] = -1e30f;
            }
            pm0 = fmaxf(pm0, fmaxf(sf[nt][0], sf[nt][1]));
            pm1 = fmaxf(pm1, fmaxf(sf[nt][2], sf[nt][3]));
        }
        pm0 = fmaxf(pm0, __shfl_xor_sync(~0u, pm0, 1));
        pm0 = fmaxf(pm0, __shfl_xor_sync(~0u, pm0, 2));
        pm1 = fmaxf(pm1, __shfl_xor_sync(~0u, pm1, 1));
        pm1 = fmaxf(pm1, __shfl_xor_sync(~0u, pm1, 2));
        const float mn0 = fmaxf(m0, pm0), mn1 = fmaxf(m1, pm1);
        const float cr0 = __expf(m0 - mn0), cr1 = __expf(m1 - mn1);
        m0 = mn0; m1 = mn1;

        float ps0 = 0.f, ps1 = 0.f;
#pragma unroll
        for (int nt = 0; nt < 8; nt++) {
            sf[nt][0] = __expf(sf[nt][0] - mn0);
            sf[nt][1] = __expf(sf[nt][1] - mn0);
            sf[nt][2] = __expf(sf[nt][2] - mn1);
            sf[nt][3] = __expf(sf[nt][3] - mn1);
            ps0 += sf[nt][0] + sf[nt][1];
            ps1 += sf[nt][2] + sf[nt][3];
        }
        ps0 += __shfl_xor_sync(~0u, ps0, 1);
        ps0 += __shfl_xor_sync(~0u, ps0, 2);
        ps1 += __shfl_xor_sync(~0u, ps1, 1);
        ps1 += __shfl_xor_sync(~0u, ps1, 2);
        l0 = l0 * cr0 + ps0;
        l1 = l1 * cr1 + ps1;
#pragma unroll
        for (int nt = 0; nt < 16; nt++) {
            oa[nt][0] *= cr0; oa[nt][1] *= cr0;
            oa[nt][2] *= cr1; oa[nt][3] *= cr1;
        }

        const int krow = (lane & 7) + ((lane >> 3) & 1) * 8;
        const int vcol0 = (lane >> 4) << 3;
#pragma unroll
        for (int kc = 0; kc < 4; kc++) {
            uint32_t pf[4];
            pf[0] = packh2(sf[2 * kc][0],     sf[2 * kc][1]);
            pf[1] = packh2(sf[2 * kc][2],     sf[2 * kc][3]);
            pf[2] = packh2(sf[2 * kc + 1][0], sf[2 * kc + 1][1]);
            pf[3] = packh2(sf[2 * kc + 1][2], sf[2 * kc + 1][3]);
#pragma unroll
            for (int np = 0; np < 8; np++) {
                uint32_t b0, b1, b2, b3;
                const uint32_t addr =
                    vbase + ((kc * 16 + krow) * VPH + vcol0 + np * 16) * 2;
                ldsm_x4_t(b0, b1, b2, b3, addr);
                mma_f16(oa[np * 2],     pf[0], pf[1], pf[2], pf[3], b0, b1);
                mma_f16(oa[np * 2 + 1], pf[0], pf[1], pf[2], pf[3], b2, b3);
            }
        }
    }

    const float i0 = 1.f / l0, i1 = 1.f / l1;
#pragma unroll
    for (int nt = 0; nt < 16; nt++) {
        const int c = nt * 8 + 2 * t;
        __half* o0 = out + (size_t)r0g * (NH * VD) + h * VD + c;
        *(__half2*)o0 = __floats2half2_rn(oa[nt][0] * i0, oa[nt][1] * i0);
        *(__half2*)(o0 + (size_t)8 * (NH * VD)) =
            __floats2half2_rn(oa[nt][2] * i1, oa[nt][3] * i1);
    }
}

// ---------------- launch ----------------
extern "C" void kernel_launch(void* const* d_in, const int* in_sizes, int n_in,
                              void* d_out, int out_size)
{
    const float* hidden = (const float*)d_in[0];
    const float* w_q_a  = (const float*)d_in[1];
    const float* q_a_w  = (const float*)d_in[2];
    const float* w_q_b  = (const float*)d_in[3];
    const float* w_kv_a = (const float*)d_in[4];
    const float* kv_a_w = (const float*)d_in[5];
    const float* w_kv_b = (const float*)d_in[6];
    const float* w_o    = (const float*)d_in[7];
    float* out = (float*)d_out;

    float *qc;
    __half *q16, *kv16, *kpe16;
    __half *h16, *wqakva16, *wqb16, *wkvb16, *wo16;
    __half *qlat16, *ckvn16, *attn16;
    cudaGetSymbolAddress((void**)&qc,      g_qc);
    cudaGetSymbolAddress((void**)&q16,     g_q16);
    cudaGetSymbolAddress((void**)&kv16,    g_kv16);
    cudaGetSymbolAddress((void**)&kpe16,   g_kpe16);
    cudaGetSymbolAddress((void**)&h16,     g_h16);
    cudaGetSymbolAddress((void**)&wqakva16,g_wqakva16);
    cudaGetSymbolAddress((void**)&wqb16,   g_wqb16);
    cudaGetSymbolAddress((void**)&wkvb16,  g_wkvb16);
    cudaGetSymbolAddress((void**)&wo16,    g_wo16);
    cudaGetSymbolAddress((void**)&qlat16,  g_qlat16);
    cudaGetSymbolAddress((void**)&ckvn16,  g_ckvn16);
    cudaGetSymbolAddress((void**)&attn16,  g_attn16);

    cudaFuncSetAttribute(attn_mma, cudaFuncAttributeMaxDynamicSharedMemorySize,
                         ATTN_SMEM);
    cudaFuncSetAttribute(gemm_h, cudaFuncAttributeMaxDynamicSharedMemorySize,
                         GEMM_SMEM);
    cudaFuncSetAttribute(gemm34, cudaFuncAttributeMaxDynamicSharedMemorySize,
                         GEMM_SMEM);

    // 0: fused converts
    f2h_all_kernel<<<G5, 256>>>(
        hidden, h16, w_q_a, wqakva16, w_kv_a, wqakva16 + (size_t)QLORA * HID,
        w_q_b, wqb16, w_kv_b, wkvb16, w_o, wo16);
    // 1: [qlat | ckv] = hidden @ [wqa | wkva]^T   [2048, 2112]
    gemm_h<<<dim3((NC + 127) / 128, S_LEN / 128), 256, GEMM_SMEM>>>(
        h16, wqakva16, qc, S_LEN, NC, HID);
    // 2: fused rmsnorms -> fp16
    rmsnorm2_kernel<<<dim3(S_LEN, 2), 256>>>(qc, q_a_w, kv_a_w, qlat16, ckvn16);
    // 3: MERGED q-proj (pre-scaled fp16) + kv-proj (896 CTAs)
    gemm34<<<896, 256, GEMM_SMEM>>>(qlat16, wqb16, q16, ckvn16, wkvb16, kv16);
    // 4: rope (q fp16 in-place; kpe)
    rope_kernel<<<S_LEN, 544>>>(q16, qc, kpe16);
    // 5: attention
    attn_mma<<<dim3(S_LEN / 128, NH), 256, ATTN_SMEM>>>(q16, kv16, kpe16, attn16);
    // 6: out = attn @ w_o^T            [2048, 2048]
    gemm_h<<<dim3(HID / 128, S_LEN / 128), 256, GEMM_SMEM>>>(
        attn16, wo16, out, S_LEN, HID, HID);
}